// round 2
// baseline (speedup 1.0000x reference)
#include <cuda_runtime.h>
#include <math_constants.h>

// Problem constants
#define BB   8
#define NN   4096          // 64*64
#define CC   256
#define CI   32
#define NROWS (BB*NN)      // 32768
#define LOG2E 1.4426950408889634f

// Scratch: projected fy (pre-scaled by log2(e)), gx, hx. 4 MB each.
__device__ float g_fy[NROWS * CI];
__device__ float g_gx[NROWS * CI];
__device__ float g_hx[NROWS * CI];

__device__ __forceinline__ float ex2(float v) {
    float r;
    asm("ex2.approx.ftz.f32 %0, %1;" : "=f"(r) : "f"(v));
    return r;
}

// ---------------------------------------------------------------------------
// Kernel 1: projections. fy = (y @ W_fy) * log2(e), gx = x @ W_gx, hx = x @ W_hx
// Block: 128 threads = 4 warps; warp handles 4 rows, lane = output channel k.
// x/y rows staged in SMEM (broadcast reads), W read via coalesced LDG (L1-hot).
// ---------------------------------------------------------------------------
__global__ __launch_bounds__(128) void proj_kernel(
    const float* __restrict__ x, const float* __restrict__ y,
    const float* __restrict__ Wfy, const float* __restrict__ Wgx,
    const float* __restrict__ Whx)
{
    __shared__ float xs[16][CC];
    __shared__ float ys[16][CC];

    const int row0 = blockIdx.x * 16;

    // Coalesced staged copy of 16 rows of x and y
    const float4* xg = (const float4*)(x + (size_t)row0 * CC);
    const float4* yg = (const float4*)(y + (size_t)row0 * CC);
    float4* xs4 = (float4*)&xs[0][0];
    float4* ys4 = (float4*)&ys[0][0];
    #pragma unroll
    for (int i = threadIdx.x; i < 16 * CC / 4; i += 128) {
        xs4[i] = xg[i];
        ys4[i] = yg[i];
    }
    __syncthreads();

    const int warp = threadIdx.x >> 5;
    const int lane = threadIdx.x & 31;
    const int r0   = warp * 4;

    float afy[4] = {0.f, 0.f, 0.f, 0.f};
    float agx[4] = {0.f, 0.f, 0.f, 0.f};
    float ahx[4] = {0.f, 0.f, 0.f, 0.f};

    #pragma unroll 4
    for (int c = 0; c < CC; c++) {
        const float wfy = __ldg(&Wfy[c * CI + lane]);
        const float wgx = __ldg(&Wgx[c * CI + lane]);
        const float whx = __ldg(&Whx[c * CI + lane]);
        #pragma unroll
        for (int r = 0; r < 4; r++) {
            const float xv = xs[r0 + r][c];
            const float yv = ys[r0 + r][c];
            afy[r] = fmaf(yv, wfy, afy[r]);
            agx[r] = fmaf(xv, wgx, agx[r]);
            ahx[r] = fmaf(xv, whx, ahx[r]);
        }
    }

    #pragma unroll
    for (int r = 0; r < 4; r++) {
        const int row = row0 + r0 + r;
        g_fy[row * CI + lane] = afy[r] * LOG2E;   // pre-scale: softmax uses exp2
        g_gx[row * CI + lane] = agx[r];
        g_hx[row * CI + lane] = ahx[r];
    }
}

// ---------------------------------------------------------------------------
// Kernel 2: streaming (flash-style) attention + fused out-proj + residual.
// Grid: (N/128 query tiles, B). Block: 128 threads; thread = one query row.
// Online softmax over key tiles of 128 staged in SMEM (broadcast LDS reads).
// Epilogue reuses the SMEM buffer for W_out^T, writes out = x + sigma*attn_g@W_out.
// ---------------------------------------------------------------------------
#define TQ 128
#define TK 128

__global__ __launch_bounds__(128) void attn_kernel(
    const float* __restrict__ x, const float* __restrict__ Wout,
    const float* __restrict__ sigma_p, float* __restrict__ out)
{
    // 32 KB: key-tile buffers, later reused for W_out^T (8192 floats exactly)
    __shared__ float smem[2 * TK * CI];
    float* gxs = smem;            // [TK][CI]
    float* hxs = smem + TK * CI;  // [TK][CI]

    const int b  = blockIdx.y;
    const int q  = blockIdx.x * TQ + threadIdx.x;   // this thread's query row
    const int rowg = b * NN + q;                    // global row

    // Query vector in registers
    float fy[CI];
    {
        const float4* f4 = (const float4*)(g_fy + (size_t)rowg * CI);
        #pragma unroll
        for (int j = 0; j < CI / 4; j++) {
            float4 v = f4[j];
            fy[4*j+0] = v.x; fy[4*j+1] = v.y; fy[4*j+2] = v.z; fy[4*j+3] = v.w;
        }
    }

    float acc[CI];
    #pragma unroll
    for (int c = 0; c < CI; c++) acc[c] = 0.f;
    float m = -CUDART_INF_F;
    float l = 0.f;

    const float4* gxb = (const float4*)(g_gx + (size_t)b * NN * CI);
    const float4* hxb = (const float4*)(g_hx + (size_t)b * NN * CI);
    float4* gxs4 = (float4*)gxs;
    float4* hxs4 = (float4*)hxs;

    for (int kt = 0; kt < NN; kt += TK) {
        __syncthreads();
        // Coalesced tile load: TK*CI floats each
        const int base = kt * CI / 4;
        #pragma unroll
        for (int i = threadIdx.x; i < TK * CI / 4; i += 128) {
            gxs4[i] = gxb[base + i];
            hxs4[i] = hxb[base + i];
        }
        __syncthreads();

        for (int kk = 0; kk < TK; kk++) {
            // score = fy . gx_row  (4 partial sums for ILP); fy pre-scaled by log2e
            const float4* grow = (const float4*)&gxs[kk * CI];
            float s0 = 0.f, s1 = 0.f, s2 = 0.f, s3 = 0.f;
            #pragma unroll
            for (int j = 0; j < CI / 4; j++) {
                float4 g = grow[j];
                s0 = fmaf(fy[4*j+0], g.x, s0);
                s1 = fmaf(fy[4*j+1], g.y, s1);
                s2 = fmaf(fy[4*j+2], g.z, s2);
                s3 = fmaf(fy[4*j+3], g.w, s3);
            }
            const float s = (s0 + s1) + (s2 + s3);

            if (s > m) {                       // rare: ~ln(N) times per row
                const float scale = ex2(m - s);
                l *= scale;
                #pragma unroll
                for (int c = 0; c < CI; c++) acc[c] *= scale;
                m = s;
            }
            const float p = ex2(s - m);
            l += p;

            const float4* hrow = (const float4*)&hxs[kk * CI];
            #pragma unroll
            for (int j = 0; j < CI / 4; j++) {
                float4 h = hrow[j];
                acc[4*j+0] = fmaf(p, h.x, acc[4*j+0]);
                acc[4*j+1] = fmaf(p, h.y, acc[4*j+1]);
                acc[4*j+2] = fmaf(p, h.z, acc[4*j+2]);
                acc[4*j+3] = fmaf(p, h.w, acc[4*j+3]);
            }
        }
    }

    // ---- Epilogue: reuse SMEM for W_out^T ([c_out][k], 8192 floats = 32 KB)
    __syncthreads();
    for (int i = threadIdx.x; i < CC * CI; i += 128) {
        const int co = i >> 5;      // output channel
        const int k  = i & 31;      // inner channel
        smem[i] = Wout[k * CC + co];
    }
    __syncthreads();

    // Fold 1/l and sigma into acc
    const float sg = __ldg(sigma_p) / l;
    #pragma unroll
    for (int c = 0; c < CI; c++) acc[c] *= sg;

    const float4* xrow = (const float4*)(x + (size_t)rowg * CC);
    float4* orow = (float4*)(out + (size_t)rowg * CC);

    for (int co = 0; co < CC; co += 4) {
        float r[4];
        #pragma unroll
        for (int u = 0; u < 4; u++) {
            const float4* w4 = (const float4*)&smem[(co + u) * CI];
            float t0 = 0.f, t1 = 0.f, t2 = 0.f, t3 = 0.f;
            #pragma unroll
            for (int j = 0; j < CI / 4; j++) {
                float4 w = w4[j];
                t0 = fmaf(acc[4*j+0], w.x, t0);
                t1 = fmaf(acc[4*j+1], w.y, t1);
                t2 = fmaf(acc[4*j+2], w.z, t2);
                t3 = fmaf(acc[4*j+3], w.w, t3);
            }
            r[u] = (t0 + t1) + (t2 + t3);
        }
        float4 xv = xrow[co / 4];
        float4 ov;
        ov.x = xv.x + r[0];
        ov.y = xv.y + r[1];
        ov.z = xv.z + r[2];
        ov.w = xv.w + r[3];
        orow[co / 4] = ov;
    }
}

// ---------------------------------------------------------------------------
extern "C" void kernel_launch(void* const* d_in, const int* in_sizes, int n_in,
                              void* d_out, int out_size)
{
    const float* x     = (const float*)d_in[0];
    const float* y     = (const float*)d_in[1];
    const float* Wfy   = (const float*)d_in[2];
    const float* Wgx   = (const float*)d_in[3];
    const float* Whx   = (const float*)d_in[4];
    const float* Wout  = (const float*)d_in[5];
    const float* sigma = (const float*)d_in[6];
    float* out = (float*)d_out;

    proj_kernel<<<NROWS / 16, 128>>>(x, y, Wfy, Wgx, Whx);
    attn_kernel<<<dim3(NN / TQ, BB), 128>>>(x, Wout, sigma, out);
}

// round 3
// speedup vs baseline: 1.1492x; 1.1492x over previous
#include <cuda_runtime.h>
#include <math_constants.h>

// Problem constants
#define BB   8
#define NN   4096          // 64*64
#define CC   256
#define CI   32
#define NROWS (BB*NN)      // 32768
#define LOG2E 1.4426950408889634f
#define SPLIT 4
#define KCHUNK (NN / SPLIT)   // 1024 keys per split

typedef unsigned long long ull;

// Scratch: projections (4 MB each) + split-K partials (~17 MB)
__device__ float g_fy[NROWS * CI];
__device__ float g_gx[NROWS * CI];
__device__ float g_hx[NROWS * CI];
__device__ float g_pm [SPLIT * NROWS];
__device__ float g_pl [SPLIT * NROWS];
__device__ float g_pacc[SPLIT * NROWS * CI];

__device__ __forceinline__ float ex2(float v) {
    float r;
    asm("ex2.approx.ftz.f32 %0, %1;" : "=f"(r) : "f"(v));
    return r;
}

// ---- packed f32x2 helpers (sm_100+) --------------------------------------
__device__ __forceinline__ ull pack2(float lo, float hi) {
    ull r; asm("mov.b64 %0, {%1, %2};" : "=l"(r) : "f"(lo), "f"(hi)); return r;
}
__device__ __forceinline__ void unpack2(ull v, float& lo, float& hi) {
    asm("mov.b64 {%0, %1}, %2;" : "=f"(lo), "=f"(hi) : "l"(v));
}
__device__ __forceinline__ ull fma2(ull a, ull b, ull c) {
    ull d; asm("fma.rn.f32x2 %0, %1, %2, %3;" : "=l"(d) : "l"(a), "l"(b), "l"(c)); return d;
}
__device__ __forceinline__ ull mul2(ull a, ull b) {
    ull d; asm("mul.rn.f32x2 %0, %1, %2;" : "=l"(d) : "l"(a), "l"(b)); return d;
}

// ---------------------------------------------------------------------------
// Kernel 1: projections. fy = (y @ W_fy) * log2(e), gx = x @ W_gx, hx = x @ W_hx
// ---------------------------------------------------------------------------
__global__ __launch_bounds__(128) void proj_kernel(
    const float* __restrict__ x, const float* __restrict__ y,
    const float* __restrict__ Wfy, const float* __restrict__ Wgx,
    const float* __restrict__ Whx)
{
    __shared__ float xs[16][CC];
    __shared__ float ys[16][CC];

    const int row0 = blockIdx.x * 16;
    const float4* xg = (const float4*)(x + (size_t)row0 * CC);
    const float4* yg = (const float4*)(y + (size_t)row0 * CC);
    float4* xs4 = (float4*)&xs[0][0];
    float4* ys4 = (float4*)&ys[0][0];
    #pragma unroll
    for (int i = threadIdx.x; i < 16 * CC / 4; i += 128) {
        xs4[i] = xg[i];
        ys4[i] = yg[i];
    }
    __syncthreads();

    const int warp = threadIdx.x >> 5;
    const int lane = threadIdx.x & 31;
    const int r0   = warp * 4;

    float afy[4] = {0.f, 0.f, 0.f, 0.f};
    float agx[4] = {0.f, 0.f, 0.f, 0.f};
    float ahx[4] = {0.f, 0.f, 0.f, 0.f};

    #pragma unroll 4
    for (int c = 0; c < CC; c++) {
        const float wfy = __ldg(&Wfy[c * CI + lane]);
        const float wgx = __ldg(&Wgx[c * CI + lane]);
        const float whx = __ldg(&Whx[c * CI + lane]);
        #pragma unroll
        for (int r = 0; r < 4; r++) {
            const float xv = xs[r0 + r][c];
            const float yv = ys[r0 + r][c];
            afy[r] = fmaf(yv, wfy, afy[r]);
            agx[r] = fmaf(xv, wgx, agx[r]);
            ahx[r] = fmaf(xv, whx, ahx[r]);
        }
    }

    #pragma unroll
    for (int r = 0; r < 4; r++) {
        const int row = row0 + r0 + r;
        g_fy[row * CI + lane] = afy[r] * LOG2E;   // pre-scale: softmax uses exp2
        g_gx[row * CI + lane] = agx[r];
        g_hx[row * CI + lane] = ahx[r];
    }
}

// ---------------------------------------------------------------------------
// Kernel 2: split-K streaming attention. grid = (N/TQ, B, SPLIT).
// Thread = one query row; each block covers KCHUNK keys; partial (m, l, acc)
// written to global scratch. Inner loop uses packed f32x2 FMAs.
// ---------------------------------------------------------------------------
#define TQ 128
#define TK 128

__global__ __launch_bounds__(128) void attn_split_kernel()
{
    __shared__ float smem[2 * TK * CI];   // 32 KB
    float* gxs = smem;
    float* hxs = smem + TK * CI;

    const int b    = blockIdx.y;
    const int z    = blockIdx.z;
    const int q    = blockIdx.x * TQ + threadIdx.x;
    const int rowg = b * NN + q;

    // Query vector as 16 packed f32x2
    ull fy2[CI / 2];
    {
        const ulonglong2* f2 = (const ulonglong2*)(g_fy + (size_t)rowg * CI);
        #pragma unroll
        for (int j = 0; j < CI / 4; j++) {
            ulonglong2 v = f2[j];
            fy2[2*j]   = v.x;
            fy2[2*j+1] = v.y;
        }
    }

    ull acc2[CI / 2];
    #pragma unroll
    for (int c = 0; c < CI / 2; c++) acc2[c] = 0ull;
    float m = -CUDART_INF_F;
    float l = 0.f;

    const int k0 = z * KCHUNK;
    const float4* gxb = (const float4*)(g_gx + ((size_t)b * NN + k0) * CI);
    const float4* hxb = (const float4*)(g_hx + ((size_t)b * NN + k0) * CI);
    float4* gxs4 = (float4*)gxs;
    float4* hxs4 = (float4*)hxs;

    for (int kt = 0; kt < KCHUNK; kt += TK) {
        __syncthreads();
        const int base = kt * CI / 4;
        #pragma unroll
        for (int i = threadIdx.x; i < TK * CI / 4; i += 128) {
            gxs4[i] = gxb[base + i];
            hxs4[i] = hxb[base + i];
        }
        __syncthreads();

        for (int kk = 0; kk < TK; kk++) {
            // score = fy . gx_row via 16 packed FMAs on 4 chains
            const ulonglong2* grow = (const ulonglong2*)&gxs[kk * CI];
            ull a0 = 0ull, a1 = 0ull, a2 = 0ull, a3 = 0ull;
            #pragma unroll
            for (int j = 0; j < CI / 8; j++) {       // 4 iterations
                ulonglong2 ga = grow[2*j];
                ulonglong2 gb = grow[2*j + 1];
                a0 = fma2(fy2[4*j+0], ga.x, a0);
                a1 = fma2(fy2[4*j+1], ga.y, a1);
                a2 = fma2(fy2[4*j+2], gb.x, a2);
                a3 = fma2(fy2[4*j+3], gb.y, a3);
            }
            float x0, x1, x2, x3, x4, x5, x6, x7;
            unpack2(a0, x0, x1); unpack2(a1, x2, x3);
            unpack2(a2, x4, x5); unpack2(a3, x6, x7);
            const float s = ((x0 + x1) + (x2 + x3)) + ((x4 + x5) + (x6 + x7));

            if (s > m) {                        // rare after warmup
                const float scale = ex2(m - s);
                l *= scale;
                const ull sc2 = pack2(scale, scale);
                #pragma unroll
                for (int c = 0; c < CI / 2; c++) acc2[c] = mul2(sc2, acc2[c]);
                m = s;
            }
            const float p = ex2(s - m);
            l += p;
            const ull pp = pack2(p, p);

            const ulonglong2* hrow = (const ulonglong2*)&hxs[kk * CI];
            #pragma unroll
            for (int j = 0; j < CI / 4; j++) {       // 8 iterations, 16 packed FMAs
                ulonglong2 h = hrow[j];
                acc2[2*j]   = fma2(pp, h.x, acc2[2*j]);
                acc2[2*j+1] = fma2(pp, h.y, acc2[2*j+1]);
            }
        }
    }

    // Store partials (m in log2 domain, unnormalized acc)
    const size_t pidx = (size_t)z * NROWS + rowg;
    g_pm[pidx] = m;
    g_pl[pidx] = l;
    float4* pacc = (float4*)(g_pacc + pidx * CI);
    #pragma unroll
    for (int j = 0; j < CI / 4; j++) {
        float lo0, hi0, lo1, hi1;
        unpack2(acc2[2*j], lo0, hi0);
        unpack2(acc2[2*j+1], lo1, hi1);
        pacc[j] = make_float4(lo0, hi0, lo1, hi1);
    }
}

// ---------------------------------------------------------------------------
// Kernel 3: merge partials + out-projection + residual.
// Thread = one query row. W_out^T staged in SMEM.
// ---------------------------------------------------------------------------
__global__ __launch_bounds__(128) void merge_kernel(
    const float* __restrict__ x, const float* __restrict__ Wout,
    const float* __restrict__ sigma_p, float* __restrict__ out)
{
    __shared__ float wsm[CC * CI];   // W_out^T: [c_out][k], 32 KB

    for (int i = threadIdx.x; i < CC * CI; i += 128) {
        const int co = i >> 5;
        const int k  = i & 31;
        wsm[i] = Wout[k * CC + co];
    }
    __syncthreads();

    const int rowg = blockIdx.x * 128 + threadIdx.x;

    // Global max over splits
    float M = -CUDART_INF_F;
    float pm[SPLIT];
    #pragma unroll
    for (int zz = 0; zz < SPLIT; zz++) {
        pm[zz] = g_pm[(size_t)zz * NROWS + rowg];
        M = fmaxf(M, pm[zz]);
    }

    float acc[CI];
    #pragma unroll
    for (int c = 0; c < CI; c++) acc[c] = 0.f;
    float L = 0.f;

    #pragma unroll
    for (int zz = 0; zz < SPLIT; zz++) {
        const size_t pidx = (size_t)zz * NROWS + rowg;
        const float w = ex2(pm[zz] - M);          // log2-domain rescale
        L += g_pl[pidx] * w;
        const float4* pacc = (const float4*)(g_pacc + pidx * CI);
        #pragma unroll
        for (int j = 0; j < CI / 4; j++) {
            float4 v = pacc[j];
            acc[4*j+0] = fmaf(w, v.x, acc[4*j+0]);
            acc[4*j+1] = fmaf(w, v.y, acc[4*j+1]);
            acc[4*j+2] = fmaf(w, v.z, acc[4*j+2]);
            acc[4*j+3] = fmaf(w, v.w, acc[4*j+3]);
        }
    }

    const float sg = __ldg(sigma_p) / L;
    #pragma unroll
    for (int c = 0; c < CI; c++) acc[c] *= sg;

    const float4* xrow = (const float4*)(x + (size_t)rowg * CC);
    float4* orow = (float4*)(out + (size_t)rowg * CC);

    for (int co = 0; co < CC; co += 4) {
        float r[4];
        #pragma unroll
        for (int u = 0; u < 4; u++) {
            const float4* w4 = (const float4*)&wsm[(co + u) * CI];
            float t0 = 0.f, t1 = 0.f, t2 = 0.f, t3 = 0.f;
            #pragma unroll
            for (int j = 0; j < CI / 4; j++) {
                float4 w = w4[j];
                t0 = fmaf(acc[4*j+0], w.x, t0);
                t1 = fmaf(acc[4*j+1], w.y, t1);
                t2 = fmaf(acc[4*j+2], w.z, t2);
                t3 = fmaf(acc[4*j+3], w.w, t3);
            }
            r[u] = (t0 + t1) + (t2 + t3);
        }
        float4 xv = xrow[co / 4];
        float4 ov;
        ov.x = xv.x + r[0];
        ov.y = xv.y + r[1];
        ov.z = xv.z + r[2];
        ov.w = xv.w + r[3];
        orow[co / 4] = ov;
    }
}

// ---------------------------------------------------------------------------
extern "C" void kernel_launch(void* const* d_in, const int* in_sizes, int n_in,
                              void* d_out, int out_size)
{
    const float* x     = (const float*)d_in[0];
    const float* y     = (const float*)d_in[1];
    const float* Wfy   = (const float*)d_in[2];
    const float* Wgx   = (const float*)d_in[3];
    const float* Whx   = (const float*)d_in[4];
    const float* Wout  = (const float*)d_in[5];
    const float* sigma = (const float*)d_in[6];
    float* out = (float*)d_out;

    proj_kernel<<<NROWS / 16, 128>>>(x, y, Wfy, Wgx, Whx);
    attn_split_kernel<<<dim3(NN / TQ, BB, SPLIT), 128>>>();
    merge_kernel<<<NROWS / 128, 128>>>(x, Wout, sigma, out);
}

// round 6
// speedup vs baseline: 2.1128x; 1.8385x over previous
#include <cuda_runtime.h>
#include <cuda_bf16.h>
#include <cstdint>

#define BB 8
#define NN 4096
#define CC 256
#define CI 32
#define NROWS (BB*NN)
#define LOG2E 1.4426950408889634f
#define NTILE 32           // 4096 keys / 128 per tile

typedef unsigned long long ull;

// Scratch (global): fy f32 (log2e-prescaled), gx/hx bf16 hi+lo splits.
__device__ float         g_fy [NROWS * CI];
__device__ __nv_bfloat16 g_gxh[NROWS * CI];   // [b*N + key][ci]
__device__ __nv_bfloat16 g_gxl[NROWS * CI];
__device__ __nv_bfloat16 g_hxh[NROWS * CI];   // [(b*CI + ci)][key] transposed
__device__ __nv_bfloat16 g_hxl[NROWS * CI];

// ---------------- helpers ----------------
__device__ __forceinline__ float ex2(float v) {
    float r; asm("ex2.approx.ftz.f32 %0, %1;" : "=f"(r) : "f"(v)); return r;
}
__device__ __forceinline__ ull pack2(float lo, float hi) {
    ull r; asm("mov.b64 %0, {%1, %2};" : "=l"(r) : "f"(lo), "f"(hi)); return r;
}
__device__ __forceinline__ void unpack2(ull v, float& lo, float& hi) {
    asm("mov.b64 {%0, %1}, %2;" : "=f"(lo), "=f"(hi) : "l"(v));
}
__device__ __forceinline__ ull fma2(ull a, ull b, ull c) {
    ull d; asm("fma.rn.f32x2 %0, %1, %2, %3;" : "=l"(d) : "l"(a), "l"(b), "l"(c)); return d;
}
__device__ __forceinline__ void split1(float v, uint16_t& h, uint16_t& l) {
    __nv_bfloat16 hb = __float2bfloat16_rn(v);
    __nv_bfloat16 lb = __float2bfloat16_rn(v - __bfloat162float(hb));
    h = __bfloat16_as_ushort(hb);
    l = __bfloat16_as_ushort(lb);
}
__device__ __forceinline__ void split_pack(float a, float b, uint32_t& hi, uint32_t& lo) {
    uint16_t ha, la, hb, lb;
    split1(a, ha, la); split1(b, hb, lb);
    hi = (uint32_t)ha | ((uint32_t)hb << 16);
    lo = (uint32_t)la | ((uint32_t)lb << 16);
}

// mma.sync m16n8k16 row.col f32.bf16.bf16.f32 (HMMA; supported on base sm_100)
__device__ __forceinline__ void mma_bf16(float* d, const uint32_t* a, const uint32_t* b) {
    asm volatile(
        "mma.sync.aligned.m16n8k16.row.col.f32.bf16.bf16.f32 "
        "{%0,%1,%2,%3}, {%4,%5,%6,%7}, {%8,%9}, {%0,%1,%2,%3};"
        : "+f"(d[0]), "+f"(d[1]), "+f"(d[2]), "+f"(d[3])
        : "r"(a[0]), "r"(a[1]), "r"(a[2]), "r"(a[3]), "r"(b[0]), "r"(b[1]));
}

// ---------------------------------------------------------------------------
// Kernel 1: projections + bf16 hi/lo splits (fy kept f32, log2e-prescaled).
// ---------------------------------------------------------------------------
__global__ __launch_bounds__(128) void proj_kernel(
    const float* __restrict__ x, const float* __restrict__ y,
    const float* __restrict__ Wfy, const float* __restrict__ Wgx,
    const float* __restrict__ Whx)
{
    __shared__ float xs[16][CC];
    __shared__ float ys[16][CC];

    const int row0 = blockIdx.x * 16;
    const float4* xg = (const float4*)(x + (size_t)row0 * CC);
    const float4* yg = (const float4*)(y + (size_t)row0 * CC);
    float4* xs4 = (float4*)&xs[0][0];
    float4* ys4 = (float4*)&ys[0][0];
    #pragma unroll
    for (int i = threadIdx.x; i < 16 * CC / 4; i += 128) {
        xs4[i] = xg[i];
        ys4[i] = yg[i];
    }
    __syncthreads();

    const int warp = threadIdx.x >> 5;
    const int lane = threadIdx.x & 31;
    const int r0   = warp * 4;

    float afy[4] = {0.f, 0.f, 0.f, 0.f};
    float agx[4] = {0.f, 0.f, 0.f, 0.f};
    float ahx[4] = {0.f, 0.f, 0.f, 0.f};

    #pragma unroll 4
    for (int c = 0; c < CC; c++) {
        const float wfy = __ldg(&Wfy[c * CI + lane]);
        const float wgx = __ldg(&Wgx[c * CI + lane]);
        const float whx = __ldg(&Whx[c * CI + lane]);
        #pragma unroll
        for (int r = 0; r < 4; r++) {
            const float xv = xs[r0 + r][c];
            const float yv = ys[r0 + r][c];
            afy[r] = fmaf(yv, wfy, afy[r]);
            agx[r] = fmaf(xv, wgx, agx[r]);
            ahx[r] = fmaf(xv, whx, ahx[r]);
        }
    }

    #pragma unroll
    for (int r = 0; r < 4; r++) {
        const int row = row0 + r0 + r;
        const int b = row >> 12;
        const int n = row & (NN - 1);
        g_fy[row * CI + lane] = afy[r] * LOG2E;

        uint16_t h, l;
        split1(agx[r], h, l);
        g_gxh[row * CI + lane] = __ushort_as_bfloat16(h);
        g_gxl[row * CI + lane] = __ushort_as_bfloat16(l);

        split1(ahx[r], h, l);
        const size_t ti = ((size_t)(b * CI + lane)) * NN + n;
        g_hxh[ti] = __ushort_as_bfloat16(h);
        g_hxl[ti] = __ushort_as_bfloat16(l);
    }
}

// ---------------------------------------------------------------------------
// Kernel 2: FA2-style flash attention on mma.sync (HMMA), no-max softmax,
// fused out-projection + residual. CTA = 64 q rows (4 warps x m16), 128 thr.
// ---------------------------------------------------------------------------
__global__ __launch_bounds__(128) void attn_mma_kernel(
    const float* __restrict__ x, const float* __restrict__ Wout,
    const float* __restrict__ sigma_p, float* __restrict__ out)
{
    __shared__ union {
        struct {                       // tile phase (padded, conflict-free frags)
            uint32_t gxh[128 * 20];    // gx hi: [key][16 uints], stride 20
            uint32_t gxl[128 * 20];
            uint32_t hxh[32 * 68];     // hxT hi: [ci][64 uints], stride 68
            uint32_t hxl[32 * 68];
        } t;
        struct {                       // epilogue phase
            float wout[CI * CC];       // [k][co] row-major (= Wout layout)
            float o[64 * 36];          // O rows, stride 36
            float l[64];
        } e;
    } smem;

    const int tid  = threadIdx.x;
    const int warp = tid >> 5;
    const int lane = tid & 31;
    const int g    = lane >> 2;        // mma group row
    const int tg   = lane & 3;         // thread-in-group
    const int b    = blockIdx.y;
    const int q0   = blockIdx.x * 64;
    const int qw   = q0 + warp * 16;   // this warp's 16 query rows

    // ---- fy A-fragments (2 k16 chunks, hi+lo)
    uint32_t fyh[2][4], fyl[2][4];
    {
        const float* fyb = g_fy + ((size_t)(b * NN + qw)) * CI;
        #pragma unroll
        for (int c = 0; c < 2; c++) {
            const int c0 = c * 16 + 2 * tg;
            float2 v0 = *(const float2*)(fyb + g * CI + c0);           // a0
            float2 v1 = *(const float2*)(fyb + (g + 8) * CI + c0);     // a1
            float2 v2 = *(const float2*)(fyb + g * CI + c0 + 8);       // a2
            float2 v3 = *(const float2*)(fyb + (g + 8) * CI + c0 + 8); // a3
            split_pack(v0.x, v0.y, fyh[c][0], fyl[c][0]);
            split_pack(v1.x, v1.y, fyh[c][1], fyl[c][1]);
            split_pack(v2.x, v2.y, fyh[c][2], fyl[c][2]);
            split_pack(v3.x, v3.y, fyh[c][3], fyl[c][3]);
        }
    }

    float o[4][4];
    #pragma unroll
    for (int i = 0; i < 4; i++)
        #pragma unroll
        for (int j = 0; j < 4; j++) o[i][j] = 0.f;
    float l0 = 0.f, l1 = 0.f;

    const uint32_t* ghb = (const uint32_t*)g_gxh + ((size_t)b * NN) * 16;
    const uint32_t* glb = (const uint32_t*)g_gxl + ((size_t)b * NN) * 16;
    const uint32_t* hhb = (const uint32_t*)g_hxh + ((size_t)b * CI) * 2048;
    const uint32_t* hlb = (const uint32_t*)g_hxl + ((size_t)b * CI) * 2048;

    for (int kt = 0; kt < NTILE; kt++) {
        __syncthreads();
        // ---- stage tiles (bf16 already split in gmem)
        {
            const uint32_t* gh = ghb + (size_t)kt * 128 * 16;
            const uint32_t* gl = glb + (size_t)kt * 128 * 16;
            #pragma unroll
            for (int i = tid; i < 2048; i += 128) {
                const int row = i >> 4, col = i & 15;
                smem.t.gxh[row * 20 + col] = gh[i];
                smem.t.gxl[row * 20 + col] = gl[i];
            }
            #pragma unroll
            for (int i = tid; i < 2048; i += 128) {
                const int row = i >> 6, col = i & 63;
                smem.t.hxh[row * 68 + col] = hhb[(size_t)row * 2048 + kt * 64 + col];
                smem.t.hxl[row * 68 + col] = hlb[(size_t)row * 2048 + kt * 64 + col];
            }
        }
        __syncthreads();

        #pragma unroll 1
        for (int n2 = 0; n2 < 8; n2++) {   // 16 keys per iteration
            float s0[4] = {0.f, 0.f, 0.f, 0.f};
            float s1[4] = {0.f, 0.f, 0.f, 0.f};
            #pragma unroll
            for (int c = 0; c < 2; c++) {
                uint32_t bh[2], bl[2];
                const int base0 = (n2 * 16 + g) * 20 + 8 * c + tg;
                bh[0] = smem.t.gxh[base0]; bh[1] = smem.t.gxh[base0 + 4];
                bl[0] = smem.t.gxl[base0]; bl[1] = smem.t.gxl[base0 + 4];
                mma_bf16(s0, fyh[c], bh);
                mma_bf16(s0, fyh[c], bl);
                mma_bf16(s0, fyl[c], bh);
                const int base1 = (n2 * 16 + 8 + g) * 20 + 8 * c + tg;
                bh[0] = smem.t.gxh[base1]; bh[1] = smem.t.gxh[base1 + 4];
                bl[0] = smem.t.gxl[base1]; bl[1] = smem.t.gxl[base1 + 4];
                mma_bf16(s1, fyh[c], bh);
                mma_bf16(s1, fyh[c], bl);
                mma_bf16(s1, fyl[c], bh);
            }
            // p = 2^s (no max subtraction; range-safe in fp32)
            const float p00 = ex2(s0[0]), p01 = ex2(s0[1]);
            const float p02 = ex2(s0[2]), p03 = ex2(s0[3]);
            const float p10 = ex2(s1[0]), p11 = ex2(s1[1]);
            const float p12 = ex2(s1[2]), p13 = ex2(s1[3]);
            l0 += (p00 + p01) + (p10 + p11);
            l1 += (p02 + p03) + (p12 + p13);

            // C->A fragment reuse: two adjacent n8 S tiles form one k16 P frag
            uint32_t ah[4], al[4];
            split_pack(p00, p01, ah[0], al[0]);
            split_pack(p02, p03, ah[1], al[1]);
            split_pack(p10, p11, ah[2], al[2]);
            split_pack(p12, p13, ah[3], al[3]);

            #pragma unroll
            for (int cib = 0; cib < 4; cib++) {
                const int base = (cib * 8 + g) * 68 + n2 * 8 + tg;
                uint32_t bh[2] = {smem.t.hxh[base], smem.t.hxh[base + 4]};
                uint32_t bl[2] = {smem.t.hxl[base], smem.t.hxl[base + 4]};
                mma_bf16(o[cib], ah, bh);
                mma_bf16(o[cib], ah, bl);
                mma_bf16(o[cib], al, bh);
            }
        }
    }

    // ---- row sums: reduce over the 4 tg lanes of each quad
    l0 += __shfl_xor_sync(0xFFFFFFFFu, l0, 1);
    l0 += __shfl_xor_sync(0xFFFFFFFFu, l0, 2);
    l1 += __shfl_xor_sync(0xFFFFFFFFu, l1, 1);
    l1 += __shfl_xor_sync(0xFFFFFFFFu, l1, 2);

    __syncthreads();                    // tile arena dead -> epilogue arena
    {
        const int r = warp * 16 + g;
        if (tg == 0) { smem.e.l[r] = l0; smem.e.l[r + 8] = l1; }
        #pragma unroll
        for (int cib = 0; cib < 4; cib++) {
            const int cc0 = cib * 8 + 2 * tg;
            smem.e.o[r * 36 + cc0]           = o[cib][0];
            smem.e.o[r * 36 + cc0 + 1]       = o[cib][1];
            smem.e.o[(r + 8) * 36 + cc0]     = o[cib][2];
            smem.e.o[(r + 8) * 36 + cc0 + 1] = o[cib][3];
        }
    }
    for (int i = tid; i < CI * CC; i += 128) smem.e.wout[i] = Wout[i];
    __syncthreads();

    // ---- out = x + (sigma/l) * O @ W_out ; thread = (row, col-half)
    const int r  = tid & 63;
    const int ch = tid >> 6;
    const int rowg = b * NN + q0 + r;
    const float sg = __ldg(sigma_p) / smem.e.l[r];

    ull oo[CI];
    #pragma unroll
    for (int k = 0; k < CI; k++) {
        const float v = smem.e.o[r * 36 + k] * sg;
        oo[k] = pack2(v, v);
    }

    const float4* xrow = (const float4*)(x + (size_t)rowg * CC);
    float4* orow = (float4*)(out + (size_t)rowg * CC);

    for (int co = ch * 128; co < ch * 128 + 128; co += 4) {
        ull r01 = 0ull, r23 = 0ull;
        #pragma unroll
        for (int k = 0; k < CI; k++) {
            const float4 w = *(const float4*)&smem.e.wout[k * CC + co];
            r01 = fma2(oo[k], pack2(w.x, w.y), r01);
            r23 = fma2(oo[k], pack2(w.z, w.w), r23);
        }
        float a0, a1, a2, a3;
        unpack2(r01, a0, a1);
        unpack2(r23, a2, a3);
        const float4 xv = xrow[co / 4];
        float4 ov;
        ov.x = xv.x + a0; ov.y = xv.y + a1; ov.z = xv.z + a2; ov.w = xv.w + a3;
        orow[co / 4] = ov;
    }
}

// ---------------------------------------------------------------------------
extern "C" void kernel_launch(void* const* d_in, const int* in_sizes, int n_in,
                              void* d_out, int out_size)
{
    const float* x     = (const float*)d_in[0];
    const float* y     = (const float*)d_in[1];
    const float* Wfy   = (const float*)d_in[2];
    const float* Wgx   = (const float*)d_in[3];
    const float* Whx   = (const float*)d_in[4];
    const float* Wout  = (const float*)d_in[5];
    const float* sigma = (const float*)d_in[6];
    float* out = (float*)d_out;

    proj_kernel<<<NROWS / 16, 128>>>(x, y, Wfy, Wgx, Whx);
    attn_mma_kernel<<<dim3(NN / 64, BB), 128>>>(x, Wout, sigma, out);
}